// round 1
// baseline (speedup 1.0000x reference)
#include <cuda_runtime.h>

#define NN  100000
#define EE  800000
#define DD  96
#define NRD 102   // D + XD

// ---- scratch (device globals; no allocation allowed) ----
__device__ float4 g_num4[NN * 24];      // [N,96] accumulator, float4-aligned
__device__ float  g_den[NN];
__device__ float  g_P[NN * DD];         // node_rep @ W1^T
__device__ float  g_Q[NN * DD];         // node_rep @ W2^T

// ---------------------------------------------------------------------------
// K0: zero accumulators, write x into node_rep columns 96..101
// ---------------------------------------------------------------------------
__global__ void init_k(const float* __restrict__ x, float* __restrict__ node_out) {
    int i = blockIdx.x * 256 + threadIdx.x;
    if (i < NN * 24) g_num4[i] = make_float4(0.f, 0.f, 0.f, 0.f);
    if (i < NN)      g_den[i] = 0.f;
    if (i < NN * 6)  node_out[(i / 6) * NRD + 96 + (i % 6)] = x[i];
}

// ---------------------------------------------------------------------------
// K1: masked scatter-sum of edge embeddings into g_num / g_den (by col)
//     one thread per (edge, 4-float quad); vector reduction atomics
// ---------------------------------------------------------------------------
__global__ void scatter_k(const int* __restrict__ ei,
                          const float* __restrict__ attr,
                          const float* __restrict__ mask) {
    int i = blockIdx.x * 256 + threadIdx.x;
    if (i >= EE * 24) return;
    int e = i / 24;
    int q = i - e * 24;
    int c = ei[EE + e];                      // col = edge_index[1]
    float m = mask[e];
    float4 v = *(const float4*)(attr + (size_t)e * 96 + q * 4);
    float* dst = ((float*)g_num4) + (size_t)c * 96 + q * 4;   // 16B aligned
    asm volatile("red.global.add.v4.f32 [%0], {%1,%2,%3,%4};"
                 :: "l"(dst), "f"(v.x * m), "f"(v.y * m), "f"(v.z * m), "f"(v.w * m)
                 : "memory");
    if (q == 0) atomicAdd(&g_den[c], m);
}

// ---------------------------------------------------------------------------
// K2: node_rep[:, :96] = num / (den + 1)
// ---------------------------------------------------------------------------
__global__ void finalize_k(float* __restrict__ node_out) {
    int i = blockIdx.x * 256 + threadIdx.x;
    if (i >= NN * 24) return;
    int n = i / 24;
    int q = i - n * 24;
    float inv = 1.f / (g_den[n] + 1.f);
    float4 v = g_num4[i];
    float* dst = node_out + (size_t)n * NRD + q * 4;
    dst[0] = v.x * inv; dst[1] = v.y * inv; dst[2] = v.z * inv; dst[3] = v.w * inv;
}

// ---------------------------------------------------------------------------
// K3: tail-row blend. Gather-before-scatter (duplicate tails write identical
//     values, matching JAX .at[].set semantics). Both branches implemented;
//     change/is_support read from device (they are inputs).
// ---------------------------------------------------------------------------
__global__ void blend_k(const int* __restrict__ change,
                        const int* __restrict__ is_support,
                        const int* __restrict__ tails,
                        const float* __restrict__ support_tail,
                        float* __restrict__ node_out) {
    if (change[0] == 0) return;
    int t = threadIdx.x;                     // 0..127
    int node = tails[t];
    float vals[NRD];
    for (int d = 0; d < NRD; d++) vals[d] = node_out[(size_t)node * NRD + d];

    if (is_support[0]) {
        __shared__ float ssum[NRD];
        for (int d = t; d < NRD; d += 128) ssum[d] = 0.f;
        __syncthreads();
        for (int d = 0; d < NRD; d++) atomicAdd(&ssum[d], vals[d]);
        __syncthreads();
        for (int d = 0; d < NRD; d++)
            node_out[(size_t)node * NRD + d] = ssum[d] * (1.f / 128.f);
    } else {
        __syncthreads();                     // all gathers done before any write
        for (int d = 0; d < NRD; d++)
            node_out[(size_t)node * NRD + d] = 0.1f * support_tail[d] + 0.9f * vals[d];
    }
}

// ---------------------------------------------------------------------------
// K4: P = node_rep @ W[:, 0:102]^T , Q = node_rep @ W[:, 102:204]^T
//     grid.z selects P vs Q. Tile: 64 nodes x 96 outs, K chunks of 34.
// ---------------------------------------------------------------------------
__global__ __launch_bounds__(256) void pq_gemm(const float* __restrict__ node_rep,
                                               const float* __restrict__ W) {
    __shared__ float sW[NRD][97];            // [k][o]
    __shared__ float sA[64][35];             // [node][k-chunk]
    int tid = threadIdx.x;
    int z = blockIdx.z;
    int n0 = blockIdx.x * 64;
    const float* Wz = W + z * NRD;           // column offset inside row of 300

    for (int i = tid; i < NRD * 96; i += 256) {
        int k = i % NRD, o = i / NRD;        // coalesced gmem, conflict-free smem
        sW[k][o] = Wz[o * 300 + k];
    }

    float acc[4][6] = {};
    int ty = tid >> 4;                        // node group (16 x 4 = 64)
    int tx = tid & 15;                        // out group  (16 x 6 = 96)

    for (int k0 = 0; k0 < NRD; k0 += 34) {
        __syncthreads();
        #pragma unroll
        for (int v = 0; v < 5; v++) {
            int f = tid + v * 256;
            if (f < 64 * 17) {
                int e = f / 17;
                int kk2 = (f - e * 17) * 2;
                int n = n0 + e;
                float2 val = (n < NN)
                    ? *(const float2*)(node_rep + (size_t)n * NRD + k0 + kk2)
                    : make_float2(0.f, 0.f);
                sA[e][kk2] = val.x; sA[e][kk2 + 1] = val.y;
            }
        }
        __syncthreads();
        #pragma unroll
        for (int kk = 0; kk < 34; kk++) {
            float a[4], w[6];
            #pragma unroll
            for (int i2 = 0; i2 < 4; i2++) a[i2] = sA[ty * 4 + i2][kk];
            #pragma unroll
            for (int j = 0; j < 6; j++) w[j] = sW[k0 + kk][tx * 6 + j];
            #pragma unroll
            for (int i2 = 0; i2 < 4; i2++)
                #pragma unroll
                for (int j = 0; j < 6; j++) acc[i2][j] += a[i2] * w[j];
        }
    }

    float* out = z ? g_Q : g_P;
    #pragma unroll
    for (int i2 = 0; i2 < 4; i2++) {
        int n = n0 + ty * 4 + i2;
        if (n < NN) {
            #pragma unroll
            for (int j = 0; j < 6; j++)
                out[(size_t)n * 96 + tx * 6 + j] = acc[i2][j];
        }
    }
}

// ---------------------------------------------------------------------------
// K5: edge_rep = attr @ W3^T + P[row] + Q[col] + b
//     Tile: 128 edges x 96 outs, full W3 (96x96) in smem, K chunks of 16.
//     Microtile 8x6 per thread (256 threads).
// ---------------------------------------------------------------------------
__global__ __launch_bounds__(256) void edge_gemm(const float* __restrict__ attr,
                                                 const float* __restrict__ W,
                                                 const float* __restrict__ b,
                                                 const int* __restrict__ ei,
                                                 float* __restrict__ out) {
    __shared__ float sW[96][97];             // [k][o]
    __shared__ float sA[128][17];            // [edge][k-chunk]
    int tid = threadIdx.x;
    int e0 = blockIdx.x * 128;

    for (int i = tid; i < 96 * 96; i += 256) {
        int k = i % 96, o = i / 96;
        sW[k][o] = W[o * 300 + 204 + k];     // W3 slice
    }

    float acc[8][6] = {};
    int ty = tid >> 4;                        // edge group (16 x 8 = 128)
    int tx = tid & 15;                        // out group  (16 x 6 = 96)

    for (int k0 = 0; k0 < 96; k0 += 16) {
        __syncthreads();
        #pragma unroll
        for (int v = 0; v < 2; v++) {
            int f = tid + v * 256;            // 512 float4 quads = 128x16
            int e = f >> 2;
            int kq = f & 3;
            float4 val = *(const float4*)(attr + (size_t)(e0 + e) * 96 + k0 + kq * 4);
            sA[e][kq * 4 + 0] = val.x; sA[e][kq * 4 + 1] = val.y;
            sA[e][kq * 4 + 2] = val.z; sA[e][kq * 4 + 3] = val.w;
        }
        __syncthreads();
        #pragma unroll
        for (int kk = 0; kk < 16; kk++) {
            float a[8], w[6];
            #pragma unroll
            for (int i2 = 0; i2 < 8; i2++) a[i2] = sA[ty * 8 + i2][kk];
            #pragma unroll
            for (int j = 0; j < 6; j++) w[j] = sW[k0 + kk][tx * 6 + j];
            #pragma unroll
            for (int i2 = 0; i2 < 8; i2++)
                #pragma unroll
                for (int j = 0; j < 6; j++) acc[i2][j] += a[i2] * w[j];
        }
    }

    float bv[6];
    #pragma unroll
    for (int j = 0; j < 6; j++) bv[j] = b[tx * 6 + j];

    #pragma unroll
    for (int i2 = 0; i2 < 8; i2++) {
        int e = e0 + ty * 8 + i2;
        int r = ei[e];
        int c = ei[EE + e];
        const float* Pr = g_P + (size_t)r * 96 + tx * 6;
        const float* Qc = g_Q + (size_t)c * 96 + tx * 6;
        float* dst = out + (size_t)e * 96 + tx * 6;
        #pragma unroll
        for (int j = 0; j < 6; j++)
            dst[j] = acc[i2][j] + Pr[j] + Qc[j] + bv[j];
    }
}

// ---------------------------------------------------------------------------
// launch: node_rep written to d_out[0 : N*102), edge_rep to d_out[N*102 : )
// ---------------------------------------------------------------------------
extern "C" void kernel_launch(void* const* d_in, const int* in_sizes, int n_in,
                              void* d_out, int out_size) {
    const int*   change = (const int*)d_in[0];
    const int*   is_sup = (const int*)d_in[1];
    // d_in[2] = head_idxs (unused)
    const int*   tails  = (const int*)d_in[3];
    const float* x      = (const float*)d_in[4];
    const int*   ei     = (const int*)d_in[5];
    const float* attr   = (const float*)d_in[6];
    const float* mask   = (const float*)d_in[7];
    // d_in[8] = num_nodes (compile-time constant)
    const float* stail  = (const float*)d_in[9];
    const float* W      = (const float*)d_in[10];
    const float* b      = (const float*)d_in[11];

    float* node_out = (float*)d_out;
    float* edge_out = node_out + (size_t)NN * NRD;

    init_k    <<<(NN * 24 + 255) / 256, 256>>>(x, node_out);
    scatter_k <<<(EE * 24 + 255) / 256, 256>>>(ei, attr, mask);
    finalize_k<<<(NN * 24 + 255) / 256, 256>>>(node_out);
    blend_k   <<<1, 128>>>(change, is_sup, tails, stail, node_out);
    pq_gemm   <<<dim3((NN + 63) / 64, 1, 2), 256>>>(node_out, W);
    edge_gemm <<<EE / 128, 256>>>(attr, W, b, ei, edge_out);
}

// round 2
// speedup vs baseline: 1.1482x; 1.1482x over previous
#include <cuda_runtime.h>

#define NN  100000
#define EE  800000
#define DD  96
#define NRD 102   // D + XD

typedef unsigned long long u64;

__device__ __forceinline__ u64 pk2(float lo, float hi) {
    u64 r; asm("mov.b64 %0,{%1,%2};" : "=l"(r) : "f"(lo), "f"(hi)); return r;
}
__device__ __forceinline__ u64 ffma2(u64 a, u64 b, u64 c) {
    u64 d; asm("fma.rn.f32x2 %0,%1,%2,%3;" : "=l"(d) : "l"(a), "l"(b), "l"(c)); return d;
}
__device__ __forceinline__ float2 up2(u64 v) {
    float2 f; asm("mov.b64 {%0,%1},%2;" : "=f"(f.x), "=f"(f.y) : "l"(v)); return f;
}

// ---- scratch (device globals; no allocation allowed) ----
__device__ __align__(16) float4 g_num4[NN * 24];   // [N,96] accumulator
__device__ float  g_den[NN];
__device__ __align__(16) float g_P[NN * DD];       // node_rep @ W1^T
__device__ __align__(16) float g_Q[NN * DD];       // node_rep @ W2^T

// ---------------------------------------------------------------------------
// K0: zero accumulators, write x into node_rep columns 96..101
// ---------------------------------------------------------------------------
__global__ void init_k(const float* __restrict__ x, float* __restrict__ node_out) {
    int i = blockIdx.x * 256 + threadIdx.x;
    if (i < NN * 24) g_num4[i] = make_float4(0.f, 0.f, 0.f, 0.f);
    if (i < NN)      g_den[i] = 0.f;
    if (i < NN * 6)  node_out[(i / 6) * NRD + 96 + (i % 6)] = x[i];
}

// ---------------------------------------------------------------------------
// K1: masked scatter-sum via vector reduction atomics (one thread per quad)
// ---------------------------------------------------------------------------
__global__ void scatter_k(const int* __restrict__ ei,
                          const float* __restrict__ attr,
                          const float* __restrict__ mask) {
    int i = blockIdx.x * 256 + threadIdx.x;
    if (i >= EE * 24) return;
    int e = i / 24;
    int q = i - e * 24;
    int c = ei[EE + e];
    float m = mask[e];
    float4 v = *(const float4*)(attr + (size_t)e * 96 + q * 4);
    float* dst = ((float*)g_num4) + (size_t)c * 96 + q * 4;
    asm volatile("red.global.add.v4.f32 [%0], {%1,%2,%3,%4};"
                 :: "l"(dst), "f"(v.x * m), "f"(v.y * m), "f"(v.z * m), "f"(v.w * m)
                 : "memory");
    if (q == 0) atomicAdd(&g_den[c], m);
}

// ---------------------------------------------------------------------------
// K2: node_rep[:, :96] = num / (den + 1)
// ---------------------------------------------------------------------------
__global__ void finalize_k(float* __restrict__ node_out) {
    int i = blockIdx.x * 256 + threadIdx.x;
    if (i >= NN * 24) return;
    int n = i / 24;
    int q = i - n * 24;
    float inv = 1.f / (g_den[n] + 1.f);
    float4 v = g_num4[i];
    float* dst = node_out + (size_t)n * NRD + q * 4;
    dst[0] = v.x * inv; dst[1] = v.y * inv; dst[2] = v.z * inv; dst[3] = v.w * inv;
}

// ---------------------------------------------------------------------------
// K3: tail-row blend, parallel: gather-all -> sync -> write-all (one block)
// ---------------------------------------------------------------------------
__global__ void blend_k(const int* __restrict__ change,
                        const int* __restrict__ is_support,
                        const int* __restrict__ tails,
                        const float* __restrict__ support_tail,
                        float* __restrict__ node_out) {
    if (change[0] == 0) return;
    const int TOT = 128 * NRD;                 // 13056
    int tid = threadIdx.x;                     // 0..1023
    float vals[13];
    int   addr[13];
    short dim[13];
    int cnt = 0;
    for (int i = tid; i < TOT; i += 1024) {
        int t = i / NRD, d = i - t * NRD;
        int node = tails[t];
        addr[cnt] = node * NRD + d;
        dim[cnt]  = (short)d;
        vals[cnt] = node_out[addr[cnt]];
        cnt++;
    }
    if (is_support[0]) {
        __shared__ float ssum[NRD];
        for (int d = tid; d < NRD; d += 1024) ssum[d] = 0.f;
        __syncthreads();
        for (int j = 0; j < cnt; j++) atomicAdd(&ssum[dim[j]], vals[j]);
        __syncthreads();
        for (int j = 0; j < cnt; j++)
            node_out[addr[j]] = ssum[dim[j]] * (1.f / 128.f);
    } else {
        __syncthreads();                       // all gathers before any write
        for (int j = 0; j < cnt; j++)
            node_out[addr[j]] = 0.1f * support_tail[dim[j]] + 0.9f * vals[j];
    }
}

// ---------------------------------------------------------------------------
// K4: P = node_rep @ W1^T , Q = node_rep @ W2^T  (grid.z selects)
//     64 nodes x 96 outs, packed f32x2 accumulators along output dim.
// ---------------------------------------------------------------------------
__global__ __launch_bounds__(256) void pq_gemm(const float* __restrict__ node_rep,
                                               const float* __restrict__ W) {
    __shared__ __align__(16) float sW[NRD][98];   // [k][o], even pad -> 8B-aligned pairs
    __shared__ __align__(16) float sA[64][35];
    int tid = threadIdx.x;
    int z = blockIdx.z;
    int n0 = blockIdx.x * 64;
    const float* Wz = W + z * NRD;

    for (int i = tid; i < NRD * 96; i += 256) {
        int k = i % NRD, o = i / NRD;
        sW[k][o] = Wz[o * 300 + k];
    }

    u64 acc[4][3] = {};
    int ty = tid >> 4;                        // 16 groups of 4 nodes
    int tx = tid & 15;                        // 16 groups of 6 outs

    for (int k0 = 0; k0 < NRD; k0 += 34) {
        __syncthreads();
        #pragma unroll
        for (int v = 0; v < 5; v++) {
            int f = tid + v * 256;
            if (f < 64 * 17) {
                int e = f / 17;
                int kk2 = (f - e * 17) * 2;
                int n = n0 + e;
                float2 val = (n < NN)
                    ? *(const float2*)(node_rep + (size_t)n * NRD + k0 + kk2)
                    : make_float2(0.f, 0.f);
                sA[e][kk2] = val.x; sA[e][kk2 + 1] = val.y;
            }
        }
        __syncthreads();
        #pragma unroll
        for (int kk = 0; kk < 34; kk++) {
            const u64* wp = (const u64*)&sW[k0 + kk][tx * 6];
            u64 w0 = wp[0], w1 = wp[1], w2 = wp[2];
            #pragma unroll
            for (int i2 = 0; i2 < 4; i2++) {
                float a = sA[ty * 4 + i2][kk];
                u64 ap = pk2(a, a);
                acc[i2][0] = ffma2(ap, w0, acc[i2][0]);
                acc[i2][1] = ffma2(ap, w1, acc[i2][1]);
                acc[i2][2] = ffma2(ap, w2, acc[i2][2]);
            }
        }
    }

    float* out = z ? g_Q : g_P;
    #pragma unroll
    for (int i2 = 0; i2 < 4; i2++) {
        int n = n0 + ty * 4 + i2;
        if (n < NN) {
            float2* dst = (float2*)(out + (size_t)n * 96 + tx * 6);
            #pragma unroll
            for (int j2 = 0; j2 < 3; j2++) dst[j2] = up2(acc[i2][j2]);
        }
    }
}

// ---------------------------------------------------------------------------
// K5: edge_rep = attr @ W3^T + P[row] + Q[col] + b
//     128 edges x 96 outs, packed f32x2 accumulators, full W3 in smem.
// ---------------------------------------------------------------------------
__global__ __launch_bounds__(256) void edge_gemm(const float* __restrict__ attr,
                                                 const float* __restrict__ W,
                                                 const float* __restrict__ b,
                                                 const int* __restrict__ ei,
                                                 float* __restrict__ out) {
    __shared__ __align__(16) float sW[96][98];
    __shared__ __align__(16) float sA[128][17];
    int tid = threadIdx.x;
    int e0 = blockIdx.x * 128;

    for (int i = tid; i < 96 * 96; i += 256) {
        int k = i % 96, o = i / 96;
        sW[k][o] = W[o * 300 + 204 + k];       // W3 slice
    }

    u64 acc[8][3] = {};
    int ty = tid >> 4;                         // 16 groups of 8 edges
    int tx = tid & 15;                         // 16 groups of 6 outs

    for (int k0 = 0; k0 < 96; k0 += 16) {
        __syncthreads();
        #pragma unroll
        for (int v = 0; v < 2; v++) {
            int f = tid + v * 256;             // 512 quads = 128 x 16
            int e = f >> 2;
            int kq = f & 3;
            float4 val = *(const float4*)(attr + (size_t)(e0 + e) * 96 + k0 + kq * 4);
            sA[e][kq * 4 + 0] = val.x; sA[e][kq * 4 + 1] = val.y;
            sA[e][kq * 4 + 2] = val.z; sA[e][kq * 4 + 3] = val.w;
        }
        __syncthreads();
        #pragma unroll
        for (int kk = 0; kk < 16; kk++) {
            const u64* wp = (const u64*)&sW[k0 + kk][tx * 6];
            u64 w0 = wp[0], w1 = wp[1], w2 = wp[2];
            #pragma unroll
            for (int i2 = 0; i2 < 8; i2++) {
                float a = sA[ty * 8 + i2][kk];
                u64 ap = pk2(a, a);
                acc[i2][0] = ffma2(ap, w0, acc[i2][0]);
                acc[i2][1] = ffma2(ap, w1, acc[i2][1]);
                acc[i2][2] = ffma2(ap, w2, acc[i2][2]);
            }
        }
    }

    float2 bv[3];
    {
        const float2* bp = (const float2*)(b + tx * 6);
        bv[0] = bp[0]; bv[1] = bp[1]; bv[2] = bp[2];
    }

    #pragma unroll
    for (int i2 = 0; i2 < 8; i2++) {
        int e = e0 + ty * 8 + i2;
        int r = ei[e];
        int c = ei[EE + e];
        const float2* Pr = (const float2*)(g_P + (size_t)r * 96 + tx * 6);
        const float2* Qc = (const float2*)(g_Q + (size_t)c * 96 + tx * 6);
        float2* dst = (float2*)(out + (size_t)e * 96 + tx * 6);
        #pragma unroll
        for (int j2 = 0; j2 < 3; j2++) {
            float2 a = up2(acc[i2][j2]);
            float2 p = Pr[j2], q = Qc[j2];
            dst[j2] = make_float2(a.x + p.x + q.x + bv[j2].x,
                                  a.y + p.y + q.y + bv[j2].y);
        }
    }
}

// ---------------------------------------------------------------------------
extern "C" void kernel_launch(void* const* d_in, const int* in_sizes, int n_in,
                              void* d_out, int out_size) {
    const int*   change = (const int*)d_in[0];
    const int*   is_sup = (const int*)d_in[1];
    const int*   tails  = (const int*)d_in[3];
    const float* x      = (const float*)d_in[4];
    const int*   ei     = (const int*)d_in[5];
    const float* attr   = (const float*)d_in[6];
    const float* mask   = (const float*)d_in[7];
    const float* stail  = (const float*)d_in[9];
    const float* W      = (const float*)d_in[10];
    const float* b      = (const float*)d_in[11];

    float* node_out = (float*)d_out;
    float* edge_out = node_out + (size_t)NN * NRD;

    init_k    <<<(NN * 24 + 255) / 256, 256>>>(x, node_out);
    scatter_k <<<(EE * 24 + 255) / 256, 256>>>(ei, attr, mask);
    finalize_k<<<(NN * 24 + 255) / 256, 256>>>(node_out);
    blend_k   <<<1, 1024>>>(change, is_sup, tails, stail, node_out);
    pq_gemm   <<<dim3((NN + 63) / 64, 1, 2), 256>>>(node_out, W);
    edge_gemm <<<EE / 128, 256>>>(attr, W, b, ei, edge_out);
}